// round 3
// baseline (speedup 1.0000x reference)
#include <cuda_runtime.h>

#define BB 4
#define CC 32
#define HH 512
#define WW 960
#define HT 128
#define WT 240
#define HW (HH * WW)
#define THW (HT * WT)

#define BLK 320          // threads per block = x-span per block (960 = 3*320)
#define MARG_LO 56       // lower staging margin (covers disp up to 48 + slack)
#define SPAN 384         // staged floats per channel (96 float4)

__device__ __forceinline__ void stage_row(float* __restrict__ dst,
                                          const float* __restrict__ src,
                                          int WS, int tid)
{
    // 96 float4 = 384 floats; threads 0..95 do one each
    for (int k = tid; k < SPAN / 4; k += BLK) {
        int g = WS + 4 * k;
        float4 v;
        if (g >= 0 && g + 3 < WW) {
            v = __ldg((const float4*)(src + g));
        } else {
            v.x = __ldg(src + min(max(g,     0), WW - 1));
            v.y = __ldg(src + min(max(g + 1, 0), WW - 1));
            v.z = __ldg(src + min(max(g + 2, 0), WW - 1));
            v.w = __ldg(src + min(max(g + 3, 0), WW - 1));
        }
        ((float4*)dst)[k] = v;
    }
}

__global__ __launch_bounds__(BLK) void tile_warp_kernel(
    const float* __restrict__ tp,   // tile_plane [B,3,HT,WT]
    const float* __restrict__ fl,   // fea_l [B,C,H,W]
    const float* __restrict__ fr,   // fea_r [B,C,H,W]
    float* __restrict__ out)        // [B,48,HT,WT]
{
    __shared__ float sbuf[2][SPAN];

    int tid = threadIdx.x;
    int blk = blockIdx.x;
    int bx = blk % 3;
    int t  = blk / 3;
    int y  = t % HH;
    int b  = t / HH;

    int x0 = bx * BLK;
    int x  = x0 + tid;
    int WS = x0 - MARG_LO;

    int tx = x >> 2, ty = y >> 2;
    int j = x & 3,  i = y & 3;

    // tile plane params
    int tbase = b * 3 * THW + ty * WT + tx;
    float d   = __ldg(tp + tbase);
    float ddx = __ldg(tp + tbase + THW);
    float ddy = __ldg(tp + tbase + 2 * THW);

    // slanted-plane disparity; center offset (ts-1)/2 = 1.5
    float disp = d + ((float)i - 1.5f) * ddy + ((float)j - 1.5f) * ddx;
    float s = (float)x - disp;          // x_src for disp_d = 0
    float f0f = floorf(s);
    float w = s - f0f;                  // same fraction for all 3 levels
    int f0 = (int)f0f;

    const float WM1 = (float)(WW - 1);
    bool vm = (s + 1.0f >= 0.0f) && (s + 1.0f <= WM1);  // disp_d = -1
    bool v0 = (s >= 0.0f)        && (s <= WM1);          // disp_d =  0
    bool vp = (s - 1.0f >= 0.0f) && (s - 1.0f <= WM1);   // disp_d = +1

    // clamped tap indices (monotone: i0 <= i1 <= i2 <= i3)
    int i0 = min(max(f0 - 1, 0), WW - 1);
    int i1 = min(max(f0,     0), WW - 1);
    int i2 = min(max(f0 + 1, 0), WW - 1);
    int i3 = min(max(f0 + 2, 0), WW - 1);

    // all taps inside the staged window?
    bool ok = (i0 >= WS) && (i3 < WS + SPAN);
    int p0 = i0 - WS, p1 = i1 - WS, p2 = i2 - WS, p3 = i3 - WS;

    const float* rowr = fr + (b * CC * HH + y) * WW;
    const float* rowl = fl + (b * CC * HH + y) * WW + x;

    float am = 0.0f, a0 = 0.0f, ap = 0.0f;

    stage_row(sbuf[0], rowr, WS, tid);
    __syncthreads();

    for (int c = 0; c < CC; c++) {
        if (c + 1 < CC)
            stage_row(sbuf[(c + 1) & 1], rowr + (c + 1) * HW, WS, tid);

        float flv = __ldg(rowl + c * HW);

        float q0, q1, q2, q3;
        if (ok) {
            const float* sb = sbuf[c & 1];
            q0 = sb[p0]; q1 = sb[p1]; q2 = sb[p2]; q3 = sb[p3];
        } else {
            const float* rp = rowr + c * HW;
            q0 = __ldg(rp + i0); q1 = __ldg(rp + i1);
            q2 = __ldg(rp + i2); q3 = __ldg(rp + i3);
        }

        // disp_d=-1: floor=f0+1 -> taps (q2,q3); 0 -> (q1,q2); +1 -> (q0,q1)
        float wm = fmaf(w, q3 - q2, q2);
        float w0 = fmaf(w, q2 - q1, q1);
        float wp = fmaf(w, q1 - q0, q0);

        float afl = fabsf(flv);
        am += vm ? fabsf(flv - wm) : afl;
        a0 += v0 ? fabsf(flv - w0) : afl;
        ap += vp ? fabsf(flv - wp) : afl;

        __syncthreads();
    }

    // tile-unshuffle channel = i*ts + j; level blocks of 16 channels
    int ch = i * 4 + j;
    int obase = (b * 48) * THW + ty * WT + tx;
    out[obase + (ch)      * THW] = am;
    out[obase + (16 + ch) * THW] = a0;
    out[obase + (32 + ch) * THW] = ap;
}

extern "C" void kernel_launch(void* const* d_in, const int* in_sizes, int n_in,
                              void* d_out, int out_size) {
    const float* tp = (const float*)d_in[0];
    const float* fl = (const float*)d_in[1];
    const float* fr = (const float*)d_in[2];
    float* out = (float*)d_out;

    int grid = BB * HH * (WW / BLK);   // 6144 blocks
    tile_warp_kernel<<<grid, BLK>>>(tp, fl, fr, out);
}

// round 8
// speedup vs baseline: 1.6596x; 1.6596x over previous
#include <cuda_runtime.h>

#define BB 4
#define CC 32
#define HH 512
#define WW 960
#define HT 128
#define WT 240
#define HW (HH * WW)
#define THW (HT * WT)

#define BLK 320          // threads per block = x-span (960 = 3*320)
#define MARG 56          // lower staging margin (disp up to ~50 + taps)
#define SPAN 384         // staged floats per channel (96 float4)
#define NV4 (SPAN / 4)   // 96
#define DEP 8            // pipeline depth (channels in flight)

__device__ __forceinline__ void cp16(float* dst, const float* src) {
    unsigned s = (unsigned)__cvta_generic_to_shared(dst);
    asm volatile("cp.async.cg.shared.global [%0], [%1], 16;\n"
                 :: "r"(s), "l"(src));
}

__device__ __forceinline__ void stage(float* __restrict__ dst,
                                      const float* __restrict__ src,
                                      int WS, int tid)
{
    if (tid < NV4) {
        int g = WS + 4 * tid;
        if (g >= 0 && g <= WW - 4) {
            cp16(dst + 4 * tid, src + g);
        } else {
            // edge blocks only: clamped scalar staging via STS
            float4 v;
            v.x = __ldg(src + min(max(g,     0), WW - 1));
            v.y = __ldg(src + min(max(g + 1, 0), WW - 1));
            v.z = __ldg(src + min(max(g + 2, 0), WW - 1));
            v.w = __ldg(src + min(max(g + 3, 0), WW - 1));
            ((float4*)dst)[tid] = v;
        }
    }
}

__global__ __launch_bounds__(BLK) void tile_warp_kernel(
    const float* __restrict__ tp,   // tile_plane [B,3,HT,WT]
    const float* __restrict__ fl,   // fea_l [B,C,H,W]
    const float* __restrict__ fr,   // fea_r [B,C,H,W]
    float* __restrict__ out)        // [B,48,HT,WT]
{
    __shared__ __align__(16) float sbuf[DEP][SPAN];

    int tid = threadIdx.x;
    int blk = blockIdx.x;
    int bx = blk % 3;
    int t  = blk / 3;
    int y  = t % HH;
    int b  = t / HH;

    int x0 = bx * BLK;
    int x  = x0 + tid;
    int WS = x0 - MARG;

    int tx = x >> 2, ty = y >> 2;
    int j = x & 3,  i = y & 3;

    int tbase = b * 3 * THW + ty * WT + tx;
    float d   = __ldg(tp + tbase);
    float ddx = __ldg(tp + tbase + THW);
    float ddy = __ldg(tp + tbase + 2 * THW);

    // slanted-plane disparity; center offset (ts-1)/2 = 1.5
    float disp = d + ((float)i - 1.5f) * ddy + ((float)j - 1.5f) * ddx;
    float s = (float)x - disp;
    float f0f = floorf(s);
    float w = s - f0f;                  // same fraction for all 3 levels
    int f0 = (int)f0f;

    const float WM1 = (float)(WW - 1);
    bool vm = (s + 1.0f >= 0.0f) && (s + 1.0f <= WM1);  // disp_d = -1
    bool v0 = (s >= 0.0f)        && (s <= WM1);          // disp_d =  0
    bool vp = (s - 1.0f >= 0.0f) && (s - 1.0f <= WM1);   // disp_d = +1

    int i0 = min(max(f0 - 1, 0), WW - 1);
    int i1 = min(max(f0,     0), WW - 1);
    int i2 = min(max(f0 + 1, 0), WW - 1);
    int i3 = min(max(f0 + 2, 0), WW - 1);

    bool ok = (i0 >= WS) && (i3 < WS + SPAN);
    int p0 = i0 - WS, p1 = i1 - WS, p2 = i2 - WS, p3 = i3 - WS;

    const float* rowr = fr + (b * CC * HH + y) * WW;
    const float* rowl = fl + (b * CC * HH + y) * WW + x;

    // prologue: fill the pipeline
    #pragma unroll
    for (int c = 0; c < DEP; c++) {
        stage(sbuf[c], rowr + c * HW, WS, tid);
        asm volatile("cp.async.commit_group;\n" ::: "memory");
    }

    float am = 0.0f, a0 = 0.0f, ap = 0.0f;
    float fv = __ldg(rowl);             // fea_l prefetch, one channel ahead

    for (int c = 0; c < CC; c++) {
        asm volatile("cp.async.wait_group %0;\n" :: "n"(DEP - 1) : "memory");
        __syncthreads();                 // channel c staged & visible

        float fvn = (c + 1 < CC) ? __ldg(rowl + (c + 1) * HW) : 0.0f;

        float q0, q1, q2, q3;
        if (ok) {
            const float* sb = sbuf[c & (DEP - 1)];
            q0 = sb[p0]; q1 = sb[p1]; q2 = sb[p2]; q3 = sb[p3];
        } else {
            const float* rp = rowr + c * HW;
            q0 = __ldg(rp + i0); q1 = __ldg(rp + i1);
            q2 = __ldg(rp + i2); q3 = __ldg(rp + i3);
        }

        // disp_d=-1: floor=f0+1 -> (q2,q3); 0 -> (q1,q2); +1 -> (q0,q1)
        float wm = fmaf(w, q3 - q2, q2);
        float w0 = fmaf(w, q2 - q1, q1);
        float wp = fmaf(w, q1 - q0, q0);

        float afl = fabsf(fv);
        am += vm ? fabsf(fv - wm) : afl;
        a0 += v0 ? fabsf(fv - w0) : afl;
        ap += vp ? fabsf(fv - wp) : afl;
        fv = fvn;

        __syncthreads();                 // everyone done reading buf c%DEP
        if (c + DEP < CC)
            stage(sbuf[c & (DEP - 1)], rowr + (c + DEP) * HW, WS, tid);
        asm volatile("cp.async.commit_group;\n" ::: "memory");  // always: keep group count invariant
    }

    // tile-unshuffle channel = i*ts + j; level blocks of 16 channels
    int ch = i * 4 + j;
    int obase = (b * 48) * THW + ty * WT + tx;
    out[obase + (ch)      * THW] = am;
    out[obase + (16 + ch) * THW] = a0;
    out[obase + (32 + ch) * THW] = ap;
}

extern "C" void kernel_launch(void* const* d_in, const int* in_sizes, int n_in,
                              void* d_out, int out_size) {
    const float* tp = (const float*)d_in[0];
    const float* fl = (const float*)d_in[1];
    const float* fr = (const float*)d_in[2];
    float* out = (float*)d_out;

    int grid = BB * HH * (WW / BLK);   // 6144 blocks
    tile_warp_kernel<<<grid, BLK>>>(tp, fl, fr, out);
}

// round 9
// speedup vs baseline: 3.2091x; 1.9337x over previous
#include <cuda_runtime.h>

#define BB 4
#define CC 32
#define HH 512
#define WW 960
#define HT 128
#define WT 240
#define HW (HH * WW)
#define THW (HT * WT)

__global__ __launch_bounds__(256, 6) void tile_warp_kernel(
    const float* __restrict__ tp,   // tile_plane [B,3,HT,WT]
    const float* __restrict__ fl,   // fea_l [B,C,H,W]
    const float* __restrict__ fr,   // fea_r [B,C,H,W]
    float* __restrict__ out)        // [B,48,HT,WT]
{
    int idx = blockIdx.x * blockDim.x + threadIdx.x;
    if (idx >= BB * HH * WW) return;

    int x = idx % WW;
    int t = idx / WW;
    int y = t % HH;
    int b = t / HH;

    int tx = x >> 2, ty = y >> 2;
    int j = x & 3,  i = y & 3;

    // tile plane params
    int tbase = b * 3 * THW + ty * WT + tx;
    float d   = __ldg(tp + tbase);
    float ddx = __ldg(tp + tbase + THW);
    float ddy = __ldg(tp + tbase + 2 * THW);

    // slanted-plane disparity; center offset (ts-1)/2 = 1.5
    float disp = d + ((float)i - 1.5f) * ddy + ((float)j - 1.5f) * ddx;
    float s = (float)x - disp;          // x_src for disp_d = 0
    float f0f = floorf(s);
    float w = s - f0f;                  // identical fraction for all 3 levels
    int f0 = (int)f0f;

    const float* lp = fl + (b * CC * HH + y) * WW + x;
    const float* rp = fr + (b * CC * HH + y) * WW;

    float am = 0.0f, a0 = 0.0f, ap = 0.0f;

    // Interior: taps f0-1..f0+2 all in [0, W-1]; three aligned float2s at
    // even base e=(f0-1)&~1 cover them; all 3 validity masks provably true.
    bool interior = (f0 >= 1) && (f0 <= WW - 6);

    if (interior) {
        int e = (f0 - 1) & ~1;          // even, 8B-aligned base
        bool odd = (f0 & 1);            // channel-invariant tap selection
        const float2* rp2 = (const float2*)(rp + e);

        #pragma unroll 8
        for (int c = 0; c < CC; c++) {
            const float2* p = rp2 + c * (HW / 2);
            float2 A = __ldg(p);
            float2 B = __ldg(p + 1);
            float2 Cv = __ldg(p + 2);
            float flv = __ldg(lp + c * HW);

            // odd f0: taps = e..e+3 = A.x A.y B.x B.y
            // even f0: taps = e+1..e+4 = A.y B.x B.y C.x
            float q0 = odd ? A.x : A.y;
            float q1 = odd ? A.y : B.x;
            float q2 = odd ? B.x : B.y;
            float q3 = odd ? B.y : Cv.x;

            // disp_d=-1: taps (q2,q3); 0: (q1,q2); +1: (q0,q1)
            float wm = fmaf(w, q3 - q2, q2);
            float w0 = fmaf(w, q2 - q1, q1);
            float wp = fmaf(w, q1 - q0, q0);

            am += fabsf(flv - wm);
            a0 += fabsf(flv - w0);
            ap += fabsf(flv - wp);
        }
    } else {
        const float WM1 = (float)(WW - 1);
        bool vm = (s + 1.0f >= 0.0f) && (s + 1.0f <= WM1);  // disp_d = -1
        bool v0 = (s >= 0.0f)        && (s <= WM1);          // disp_d =  0
        bool vp = (s - 1.0f >= 0.0f) && (s - 1.0f <= WM1);   // disp_d = +1

        int i0 = min(max(f0 - 1, 0), WW - 1);
        int i1 = min(max(f0,     0), WW - 1);
        int i2 = min(max(f0 + 1, 0), WW - 1);
        int i3 = min(max(f0 + 2, 0), WW - 1);

        #pragma unroll 8
        for (int c = 0; c < CC; c++) {
            int co = c * HW;
            float flv = __ldg(lp + co);
            float q0 = __ldg(rp + co + i0);
            float q1 = __ldg(rp + co + i1);
            float q2 = __ldg(rp + co + i2);
            float q3 = __ldg(rp + co + i3);

            float wm = fmaf(w, q3 - q2, q2);
            float w0 = fmaf(w, q2 - q1, q1);
            float wp = fmaf(w, q1 - q0, q0);

            float afl = fabsf(flv);
            am += vm ? fabsf(flv - wm) : afl;
            a0 += v0 ? fabsf(flv - w0) : afl;
            ap += vp ? fabsf(flv - wp) : afl;
        }
    }

    // tile-unshuffle channel = i*ts + j; level blocks of 16 channels
    int ch = i * 4 + j;
    int obase = (b * 48) * THW + ty * WT + tx;
    out[obase + (ch)      * THW] = am;
    out[obase + (16 + ch) * THW] = a0;
    out[obase + (32 + ch) * THW] = ap;
}

extern "C" void kernel_launch(void* const* d_in, const int* in_sizes, int n_in,
                              void* d_out, int out_size) {
    const float* tp = (const float*)d_in[0];
    const float* fl = (const float*)d_in[1];
    const float* fr = (const float*)d_in[2];
    float* out = (float*)d_out;

    int total = BB * HH * WW;
    int block = 256;
    int grid = (total + block - 1) / block;
    tile_warp_kernel<<<grid, block>>>(tp, fl, fr, out);
}

// round 13
// speedup vs baseline: 3.8294x; 1.1933x over previous
#include <cuda_runtime.h>

#define BB 4
#define CC 32
#define HH 512
#define WW 960
#define HT 128
#define WT 240
#define HW (HH * WW)
#define THW (HT * WT)

__device__ __forceinline__ void l2_prefetch(const float* p) {
    asm volatile("prefetch.global.L2 [%0];" :: "l"(p));
}

__global__ __launch_bounds__(256, 6) void tile_warp_kernel(
    const float* __restrict__ tp,   // tile_plane [B,3,HT,WT]
    const float* __restrict__ fl,   // fea_l [B,C,H,W]
    const float* __restrict__ fr,   // fea_r [B,C,H,W]
    float* __restrict__ out)        // [B,48,HT,WT]
{
    int idx = blockIdx.x * blockDim.x + threadIdx.x;
    if (idx >= BB * HH * WW) return;

    int x = idx % WW;
    int t = idx / WW;
    int y = t % HH;
    int b = t / HH;

    int tx = x >> 2, ty = y >> 2;
    int j = x & 3,  i = y & 3;

    // tile plane params
    int tbase = b * 3 * THW + ty * WT + tx;
    float d   = __ldg(tp + tbase);
    float ddx = __ldg(tp + tbase + THW);
    float ddy = __ldg(tp + tbase + 2 * THW);

    // slanted-plane disparity; center offset (ts-1)/2 = 1.5
    float disp = d + ((float)i - 1.5f) * ddy + ((float)j - 1.5f) * ddx;
    float s = (float)x - disp;          // x_src for disp_d = 0
    float f0f = floorf(s);
    float w = s - f0f;                  // identical fraction for all 3 levels
    int f0 = (int)f0f;

    const float WM1 = (float)(WW - 1);
    bool vm = (s + 1.0f >= 0.0f) && (s + 1.0f <= WM1);  // disp_d = -1
    bool v0 = (s >= 0.0f)        && (s <= WM1);          // disp_d =  0
    bool vp = (s - 1.0f >= 0.0f) && (s - 1.0f <= WM1);   // disp_d = +1

    int i0 = min(max(f0 - 1, 0), WW - 1);
    int i1 = min(max(f0,     0), WW - 1);
    int i2 = min(max(f0 + 1, 0), WW - 1);
    int i3 = min(max(f0 + 2, 0), WW - 1);

    const float* lp = fl + (b * CC * HH + y) * WW + x;
    const float* rp = fr + (b * CC * HH + y) * WW;

    float am = 0.0f, a0 = 0.0f, ap = 0.0f;

    // Prefetch the first 8 channels' gather rows into L2.
    #pragma unroll
    for (int c = 0; c < 8; c++)
        l2_prefetch(rp + c * HW + i1);

    #pragma unroll 8
    for (int c = 0; c < CC; c++) {
        int co = c * HW;
        if (c + 8 < CC)
            l2_prefetch(rp + co + 8 * HW + i1);

        float flv = __ldg(lp + co);
        float q0 = __ldg(rp + co + i0);
        float q1 = __ldg(rp + co + i1);
        float q2 = __ldg(rp + co + i2);
        float q3 = __ldg(rp + co + i3);

        // disp_d=-1: floor = f0+1 -> taps (q2,q3); 0 -> (q1,q2); +1 -> (q0,q1)
        float wm = fmaf(w, q3 - q2, q2);
        float w0 = fmaf(w, q2 - q1, q1);
        float wp = fmaf(w, q1 - q0, q0);

        float afl = fabsf(flv);
        am += vm ? fabsf(flv - wm) : afl;
        a0 += v0 ? fabsf(flv - w0) : afl;
        ap += vp ? fabsf(flv - wp) : afl;
    }

    // tile-unshuffle channel = i*ts + j; level blocks of 16 channels
    int ch = i * 4 + j;
    int obase = (b * 48) * THW + ty * WT + tx;
    out[obase + (ch)      * THW] = am;
    out[obase + (16 + ch) * THW] = a0;
    out[obase + (32 + ch) * THW] = ap;
}

extern "C" void kernel_launch(void* const* d_in, const int* in_sizes, int n_in,
                              void* d_out, int out_size) {
    const float* tp = (const float*)d_in[0];
    const float* fl = (const float*)d_in[1];
    const float* fr = (const float*)d_in[2];
    float* out = (float*)d_out;

    int total = BB * HH * WW;
    int block = 256;
    int grid = (total + block - 1) / block;
    tile_warp_kernel<<<grid, block>>>(tp, fl, fr, out);
}